// round 2
// baseline (speedup 1.0000x reference)
#include <cuda_runtime.h>
#include <math.h>

#define NN 8192
#define BB 4
#define CC 256
#define EE 262144
#define MM (BB*NN)

// ---- static scratch (device globals; no runtime allocation) ----
__device__ int   g_is32;
__device__ int   g_cnt[NN];
__device__ int   g_rowptr[NN + 1];
__device__ int   g_cursor[NN];
__device__ float g_invdeg[NN];
__device__ int   g_col[EE];
__device__ float g_u[(size_t)MM * CC];   // x @ W_neigh
__device__ float g_v[(size_t)MM * CC];   // x @ W_self + (b_self + b_neigh)

// ---------------- edge dtype detection + CSR build ----------------
// If edge_index is int32 (JAX x64 disabled), interpreting as int64 packs two
// random ids: high word is almost surely nonzero somewhere. If genuine int64
// with values < 8192, all high words are zero.
__global__ void k_detect(const unsigned long long* __restrict__ ei) {
    if (threadIdx.x == 0) {
        unsigned long long o = 0;
        for (int k = 0; k < 64; k++) o |= (ei[k] >> 32);
        g_is32 = (o != 0ull) ? 1 : 0;
    }
}

__global__ void k_zero() {
    int i = blockIdx.x * blockDim.x + threadIdx.x;
    if (i < NN) g_cnt[i] = 0;
}

__device__ __forceinline__ int edge_at(const void* ei, int idx, int is32) {
    return is32 ? ((const int*)ei)[idx] : (int)((const long long*)ei)[idx];
}

__global__ void k_count(const void* __restrict__ ei) {
    int e = blockIdx.x * blockDim.x + threadIdx.x;
    if (e < EE) {
        int src = edge_at(ei, e, g_is32);
        if (src >= 0 && src < NN) atomicAdd(&g_cnt[src], 1);
    }
}

__global__ void k_scan() {
    __shared__ int part[256];
    int tid = threadIdx.x;
    int base = tid * 32;
    int local[32];
    int s = 0;
#pragma unroll
    for (int k = 0; k < 32; k++) { local[k] = s; s += g_cnt[base + k]; }
    part[tid] = s;
    __syncthreads();
    if (tid == 0) {
        int acc = 0;
        for (int t = 0; t < 256; t++) { int v = part[t]; part[t] = acc; acc += v; }
    }
    __syncthreads();
    int off = part[tid];
#pragma unroll
    for (int k = 0; k < 32; k++) {
        int rp = off + local[k];
        g_rowptr[base + k] = rp;
        g_cursor[base + k] = rp;
        g_invdeg[base + k] = 1.0f / (float)(g_cnt[base + k] + 1);
    }
    if (tid == 255) g_rowptr[NN] = off + s;
}

__global__ void k_scatter(const void* __restrict__ ei) {
    int e = blockIdx.x * blockDim.x + threadIdx.x;
    if (e < EE) {
        int is32 = g_is32;
        int src = edge_at(ei, e, is32);
        int dst = edge_at(ei, EE + e, is32);
        if (src >= 0 && src < NN && dst >= 0 && dst < NN) {
            int pos = atomicAdd(&g_cursor[src], 1);
            if (pos >= 0 && pos < EE) g_col[pos] = dst;
        }
    }
}

// ---------------- fused SGEMM: [32768,256] x [256,512] ----------------
// cols 0..255   -> v = x@W_self + (b_self+b_neigh)
// cols 256..511 -> u = x@W_neigh
#define BM 128
#define BN 128
#define BK 8
#define TM 8
#define TN 8

__global__ __launch_bounds__(256, 2)
void k_sgemm(const float* __restrict__ x,
             const float* __restrict__ Ws, const float* __restrict__ bs,
             const float* __restrict__ Wn, const float* __restrict__ bn) {
    __shared__ float As[BK][BM];
    __shared__ float Bs[BK][BN];

    int bx = blockIdx.x;          // 0..3: col tile of the 512-wide logical output
    int by = blockIdx.y;          // 0..255: row tile
    int tid = threadIdx.x;
    int tx = tid & 15;            // 0..15
    int ty = tid >> 4;            // 0..15

    // A load: one float4 per thread (rows 0..127, cols 0..7 of the k-slab)
    int arow = tid >> 1;          // 0..127
    int acol = (tid & 1) * 4;     // 0 or 4
    const float* Aptr = x + (size_t)(by * BM + arow) * CC + acol;

    // B load: one float4 per thread
    int brow = tid >> 5;          // 0..7
    int bcol = (tid & 31) * 4;    // 0..124
    const float* W = (bx < 2) ? Ws : Wn;
    int ncol0 = (bx & 1) * 128;   // column offset within W (0 or 128)
    const float* Bptr = W + (size_t)brow * CC + ncol0 + bcol;

    float acc[TM][TN];
#pragma unroll
    for (int i = 0; i < TM; i++)
#pragma unroll
        for (int j = 0; j < TN; j++) acc[i][j] = 0.0f;

    float4 a4 = *(const float4*)Aptr;
    float4 b4 = *(const float4*)Bptr;

    const int NKB = CC / BK;      // 32
    for (int kb = 0; kb < NKB; kb++) {
        As[acol + 0][arow] = a4.x;
        As[acol + 1][arow] = a4.y;
        As[acol + 2][arow] = a4.z;
        As[acol + 3][arow] = a4.w;
        *(float4*)&Bs[brow][bcol] = b4;
        __syncthreads();

        if (kb + 1 < NKB) {
            a4 = *(const float4*)(Aptr + (kb + 1) * BK);
            b4 = *(const float4*)(Bptr + (size_t)(kb + 1) * BK * CC);
        }

#pragma unroll
        for (int kk = 0; kk < BK; kk++) {
            float ra[TM], rb[TN];
#pragma unroll
            for (int i = 0; i < TM; i++) ra[i] = As[kk][ty * TM + i];
#pragma unroll
            for (int j = 0; j < TN; j++) rb[j] = Bs[kk][tx * TN + j];
#pragma unroll
            for (int i = 0; i < TM; i++)
#pragma unroll
                for (int j = 0; j < TN; j++) acc[i][j] = fmaf(ra[i], rb[j], acc[i][j]);
        }
        __syncthreads();
    }

    // epilogue
    int c0 = ncol0 + tx * TN;     // column within the 256-wide W (0..248)
    if (bx < 2) {
        float bias[TN];
#pragma unroll
        for (int j = 0; j < TN; j++) bias[j] = bs[c0 + j] + bn[c0 + j];
#pragma unroll
        for (int i = 0; i < TM; i++) {
            int r = by * BM + ty * TM + i;
            float* p = g_v + (size_t)r * CC + c0;
            float4 o0 = make_float4(acc[i][0] + bias[0], acc[i][1] + bias[1],
                                    acc[i][2] + bias[2], acc[i][3] + bias[3]);
            float4 o1 = make_float4(acc[i][4] + bias[4], acc[i][5] + bias[5],
                                    acc[i][6] + bias[6], acc[i][7] + bias[7]);
            *(float4*)(p) = o0;
            *(float4*)(p + 4) = o1;
        }
    } else {
#pragma unroll
        for (int i = 0; i < TM; i++) {
            int r = by * BM + ty * TM + i;
            float* p = g_u + (size_t)r * CC + c0;
            float4 o0 = make_float4(acc[i][0], acc[i][1], acc[i][2], acc[i][3]);
            float4 o1 = make_float4(acc[i][4], acc[i][5], acc[i][6], acc[i][7]);
            *(float4*)(p) = o0;
            *(float4*)(p + 4) = o1;
        }
    }
}

// ---------------- gather + gelu epilogue ----------------
__device__ __forceinline__ float gelu_exact(float z) {
    return 0.5f * z * (1.0f + erff(z * 0.70710678118654752440f));
}

__global__ __launch_bounds__(256)
void k_gather(float* __restrict__ out) {
    int i = blockIdx.x;           // node
    int c = threadIdx.x;          // channel
    int start = g_rowptr[i];
    int end = g_rowptr[i + 1];
    float inv = g_invdeg[i];

    const float* u0 = g_u + (size_t)(0 * NN) * CC + c;
    const float* u1 = g_u + (size_t)(1 * NN) * CC + c;
    const float* u2 = g_u + (size_t)(2 * NN) * CC + c;
    const float* u3 = g_u + (size_t)(3 * NN) * CC + c;

    // self loop (the +eye term)
    float a0 = u0[(size_t)i * CC];
    float a1 = u1[(size_t)i * CC];
    float a2 = u2[(size_t)i * CC];
    float a3 = u3[(size_t)i * CC];

    int p = start;
    for (; p + 1 < end; p += 2) {
        int j0 = g_col[p];
        int j1 = g_col[p + 1];
        size_t o0 = (size_t)j0 * CC;
        size_t o1 = (size_t)j1 * CC;
        a0 += u0[o0] + u0[o1];
        a1 += u1[o0] + u1[o1];
        a2 += u2[o0] + u2[o1];
        a3 += u3[o0] + u3[o1];
    }
    if (p < end) {
        size_t o = (size_t)g_col[p] * CC;
        a0 += u0[o];
        a1 += u1[o];
        a2 += u2[o];
        a3 += u3[o];
    }

    size_t m0 = ((size_t)(0 * NN + i)) * CC + c;
    size_t m1 = ((size_t)(1 * NN + i)) * CC + c;
    size_t m2 = ((size_t)(2 * NN + i)) * CC + c;
    size_t m3 = ((size_t)(3 * NN + i)) * CC + c;
    out[m0] = gelu_exact(g_v[m0] + a0 * inv);
    out[m1] = gelu_exact(g_v[m1] + a1 * inv);
    out[m2] = gelu_exact(g_v[m2] + a2 * inv);
    out[m3] = gelu_exact(g_v[m3] + a3 * inv);
}

// ---------------- launch ----------------
extern "C" void kernel_launch(void* const* d_in, const int* in_sizes, int n_in,
                              void* d_out, int out_size) {
    // Map inputs by element count (robust to metadata ordering surprises).
    const float* x = 0; const void* ei = 0;
    const float* Ws = 0; const float* bsv = 0;
    const float* Wn = 0; const float* bnv = 0;
    for (int i = 0; i < n_in; i++) {
        int s = in_sizes[i];
        if (s == BB * NN * CC)      x = (const float*)d_in[i];
        else if (s == 2 * EE)       ei = d_in[i];
        else if (s == CC * CC) { if (!Ws) Ws = (const float*)d_in[i]; else Wn = (const float*)d_in[i]; }
        else if (s == CC)      { if (!bsv) bsv = (const float*)d_in[i]; else bnv = (const float*)d_in[i]; }
    }
    float* out = (float*)d_out;

    k_detect<<<1, 32>>>((const unsigned long long*)ei);
    k_zero<<<NN / 256, 256>>>();
    k_count<<<EE / 256, 256>>>(ei);
    k_scan<<<1, 256>>>();
    k_scatter<<<EE / 256, 256>>>(ei);

    dim3 ggrid(512 / BN, MM / BM);   // (4, 256)
    k_sgemm<<<ggrid, 256>>>(x, Ws, bsv, Wn, bnv);

    k_gather<<<NN, 256>>>(out);
}

// round 6
// speedup vs baseline: 1.4690x; 1.4690x over previous
#include <cuda_runtime.h>
#include <cuda_bf16.h>
#include <math.h>
#include <stdint.h>

#define NN 8192
#define BB 4
#define CC 256
#define EE 262144
#define MM (BB*NN)
#define KK 512          // GEMM K = 2*CC  ([x | y])

// ---- static scratch ----
__device__ int      g_is32;
__device__ int      g_cnt[NN];
__device__ int      g_rowptr[NN + 1];
__device__ int      g_cursor[NN];
__device__ float    g_invdeg[NN];
__device__ int      g_col[EE];
__device__ float    g_y[(size_t)MM * CC];          // y = A_hat @ x
__device__ uint32_t g_whl[(size_t)CC * KK];        // W^T split: [n][k] packed (hi | lo<<16)

// ================= edge dtype detection + CSR build =================
__global__ void k_detect(const unsigned long long* __restrict__ ei) {
    if (threadIdx.x == 0) {
        unsigned long long o = 0;
        for (int k = 0; k < 64; k++) o |= (ei[k] >> 32);
        g_is32 = (o != 0ull) ? 1 : 0;
    }
}

__global__ void k_zero() {
    int i = blockIdx.x * blockDim.x + threadIdx.x;
    if (i < NN) g_cnt[i] = 0;
}

__device__ __forceinline__ int edge_at(const void* ei, int idx, int is32) {
    return is32 ? ((const int*)ei)[idx] : (int)((const long long*)ei)[idx];
}

__global__ void k_count(const void* __restrict__ ei) {
    int e = blockIdx.x * blockDim.x + threadIdx.x;
    if (e < EE) {
        int src = edge_at(ei, e, g_is32);
        if (src >= 0 && src < NN) atomicAdd(&g_cnt[src], 1);
    }
}

__global__ __launch_bounds__(1024)
void k_scan() {      // 1024 threads, 8 elems each
    __shared__ int wsum[32];
    int tid = threadIdx.x;
    int lane = tid & 31, warp = tid >> 5;
    int base = tid * 8;
    int local[8];
    int s = 0;
#pragma unroll
    for (int k = 0; k < 8; k++) { local[k] = s; s += g_cnt[base + k]; }
    int inc = s;
#pragma unroll
    for (int off = 1; off < 32; off <<= 1) {
        int v = __shfl_up_sync(0xffffffffu, inc, off);
        if (lane >= off) inc += v;
    }
    if (lane == 31) wsum[warp] = inc;
    __syncthreads();
    if (tid < 32) {
        int v = wsum[tid];
        int inc2 = v;
#pragma unroll
        for (int off = 1; off < 32; off <<= 1) {
            int u = __shfl_up_sync(0xffffffffu, inc2, off);
            if (tid >= off) inc2 += u;
        }
        wsum[tid] = inc2 - v;   // exclusive
    }
    __syncthreads();
    int off0 = wsum[warp] + (inc - s);
#pragma unroll
    for (int k = 0; k < 8; k++) {
        int rp = off0 + local[k];
        g_rowptr[base + k] = rp;
        g_cursor[base + k] = rp;
        g_invdeg[base + k] = 1.0f / (float)(g_cnt[base + k] + 1);
    }
    if (tid == 1023) g_rowptr[NN] = off0 + s;
}

__global__ void k_scatter(const void* __restrict__ ei) {
    int e = blockIdx.x * blockDim.x + threadIdx.x;
    if (e < EE) {
        int is32 = g_is32;
        int src = edge_at(ei, e, is32);
        int dst = edge_at(ei, EE + e, is32);
        if (src >= 0 && src < NN && dst >= 0 && dst < NN) {
            int pos = atomicAdd(&g_cursor[src], 1);
            if (pos >= 0 && pos < EE) g_col[pos] = dst;
        }
    }
}

// ================= W prep: concat, transpose, bf16 split =================
__global__ void k_wprep(const float* __restrict__ Ws, const float* __restrict__ Wn) {
    int i = blockIdx.x * blockDim.x + threadIdx.x;   // over 512*256
    if (i >= KK * CC) return;
    int k = i / CC;
    int n = i % CC;
    float w = (k < CC) ? Ws[(size_t)k * CC + n] : Wn[(size_t)(k - CC) * CC + n];
    __nv_bfloat16 h = __float2bfloat16(w);
    __nv_bfloat16 l = __float2bfloat16(w - __bfloat162float(h));
    uint32_t ph = (uint32_t)__bfloat16_as_ushort(h);
    uint32_t pl = (uint32_t)__bfloat16_as_ushort(l);
    g_whl[(size_t)n * KK + k] = ph | (pl << 16);
}

// ================= neighbor aggregation: y = A_hat @ x =================
__global__ __launch_bounds__(256)
void k_agg(const float* __restrict__ x) {
    int i = blockIdx.x;           // node
    int c = threadIdx.x;          // channel
    int start = g_rowptr[i];
    int end = g_rowptr[i + 1];
    float inv = g_invdeg[i];

    const float* x0 = x + (size_t)(0 * NN) * CC + c;
    const float* x1 = x + (size_t)(1 * NN) * CC + c;
    const float* x2 = x + (size_t)(2 * NN) * CC + c;
    const float* x3 = x + (size_t)(3 * NN) * CC + c;

    float a0 = x0[(size_t)i * CC];
    float a1 = x1[(size_t)i * CC];
    float a2 = x2[(size_t)i * CC];
    float a3 = x3[(size_t)i * CC];

    int p = start;
    for (; p + 1 < end; p += 2) {
        int j0 = g_col[p];
        int j1 = g_col[p + 1];
        size_t o0 = (size_t)j0 * CC;
        size_t o1 = (size_t)j1 * CC;
        a0 += x0[o0] + x0[o1];
        a1 += x1[o0] + x1[o1];
        a2 += x2[o0] + x2[o1];
        a3 += x3[o0] + x3[o1];
    }
    if (p < end) {
        size_t o = (size_t)g_col[p] * CC;
        a0 += x0[o]; a1 += x1[o]; a2 += x2[o]; a3 += x3[o];
    }

    g_y[((size_t)(0 * NN + i)) * CC + c] = a0 * inv;
    g_y[((size_t)(1 * NN + i)) * CC + c] = a1 * inv;
    g_y[((size_t)(2 * NN + i)) * CC + c] = a2 * inv;
    g_y[((size_t)(3 * NN + i)) * CC + c] = a3 * inv;
}

// ================= tensor-core GEMM + bias + GELU =================
#define GBM 128
#define GBN 128
#define GBK 32
#define KTILES (KK / GBK)   // 16
#define APAD 8              // row stride 40 bf16 = 80B: 16B-aligned rows for ldmatrix

__device__ __forceinline__ void mma16816(float* c, const uint32_t* a, const uint32_t* b) {
    asm volatile(
        "mma.sync.aligned.m16n8k16.row.col.f32.bf16.bf16.f32 "
        "{%0,%1,%2,%3}, {%4,%5,%6,%7}, {%8,%9}, {%0,%1,%2,%3};"
        : "+f"(c[0]), "+f"(c[1]), "+f"(c[2]), "+f"(c[3])
        : "r"(a[0]), "r"(a[1]), "r"(a[2]), "r"(a[3]), "r"(b[0]), "r"(b[1]));
}

#define LDSM4(r0, r1, r2, r3, addr) \
    asm volatile("ldmatrix.sync.aligned.m8n8.x4.shared.b16 {%0,%1,%2,%3}, [%4];" \
                 : "=r"(r0), "=r"(r1), "=r"(r2), "=r"(r3) : "r"(addr))

__device__ __forceinline__ float gelu_exact(float z) {
    return 0.5f * z * (1.0f + erff(z * 0.70710678118654752440f));
}

__global__ __launch_bounds__(256, 1)
void k_mma(const float* __restrict__ x,
           const float* __restrict__ bs, const float* __restrict__ bn,
           float* __restrict__ out) {
    __shared__ __align__(16) __nv_bfloat16 Ah[GBM][GBK + APAD];
    __shared__ __align__(16) __nv_bfloat16 Al[GBM][GBK + APAD];
    __shared__ __align__(16) __nv_bfloat16 Bh[GBN][GBK + APAD];
    __shared__ __align__(16) __nv_bfloat16 Bl[GBN][GBK + APAD];

    const int tid = threadIdx.x;
    const int lane = tid & 31;
    const int warp = tid >> 5;
    const int warp_m = warp & 3;        // 4 warps along M (32 rows each)
    const int warp_n = warp >> 2;       // 2 warps along N (64 cols each)
    const int n0 = blockIdx.x * GBN;    // 0 or 128
    const int m0 = blockIdx.y * GBM;

    const int a_r = tid >> 3;           // 0..31
    const int a_k = (tid & 7) * 4;      // 0,4,...,28
    const int w_n = tid >> 1;           // 0..127
    const int w_k = (tid & 1) * 16;     // 0 or 16

    float acc[2][8][4];
#pragma unroll
    for (int i = 0; i < 2; i++)
#pragma unroll
        for (int j = 0; j < 8; j++)
#pragma unroll
            for (int q = 0; q < 4; q++) acc[i][j][q] = 0.0f;

    float4 pa[4];
    uint4  pw[4];

    // ---- prefetch tile 0 ----
    {
        const float* Asrc = x;
#pragma unroll
        for (int p = 0; p < 4; p++)
            pa[p] = *(const float4*)(Asrc + (size_t)(m0 + p * 32 + a_r) * CC + a_k);
        const uint32_t* wp = g_whl + (size_t)(n0 + w_n) * KK + w_k;
#pragma unroll
        for (int q = 0; q < 4; q++) pw[q] = *(const uint4*)(wp + q * 4);
    }

    for (int kt = 0; kt < KTILES; kt++) {
        // ---- store smem (fp32->bf16 hi/lo split for A) ----
#pragma unroll
        for (int p = 0; p < 4; p++) {
            int r = p * 32 + a_r;
            float v[4] = {pa[p].x, pa[p].y, pa[p].z, pa[p].w};
#pragma unroll
            for (int e = 0; e < 4; e++) {
                __nv_bfloat16 h = __float2bfloat16(v[e]);
                __nv_bfloat16 l = __float2bfloat16(v[e] - __bfloat162float(h));
                Ah[r][a_k + e] = h;
                Al[r][a_k + e] = l;
            }
        }
#pragma unroll
        for (int q = 0; q < 4; q++) {
            uint32_t ww[4] = {pw[q].x, pw[q].y, pw[q].z, pw[q].w};
#pragma unroll
            for (int e = 0; e < 4; e++) {
                int kk = w_k + q * 4 + e;
                Bh[w_n][kk] = __ushort_as_bfloat16((unsigned short)(ww[e] & 0xffffu));
                Bl[w_n][kk] = __ushort_as_bfloat16((unsigned short)(ww[e] >> 16));
            }
        }
        __syncthreads();

        // ---- prefetch next tile ----
        if (kt + 1 < KTILES) {
            int k0 = (kt + 1) * GBK;
            const float* Asrc = (k0 < CC) ? (x + k0) : (g_y + (k0 - CC));
#pragma unroll
            for (int p = 0; p < 4; p++)
                pa[p] = *(const float4*)(Asrc + (size_t)(m0 + p * 32 + a_r) * CC + a_k);
            const uint32_t* wp = g_whl + (size_t)(n0 + w_n) * KK + k0 + w_k;
#pragma unroll
            for (int q = 0; q < 4; q++) pw[q] = *(const uint4*)(wp + q * 4);
        }

        // ---- compute: 2 k16 steps ----
#pragma unroll
        for (int s = 0; s < 2; s++) {
            const int kb = s * 16;
            const int sub = lane >> 3;
            const int l8 = lane & 7;
            const int arow_off = (sub & 1) * 8 + l8;
            const int acol_off = kb + (sub >> 1) * 8;

            uint32_t ah[2][4], al[2][4];
#pragma unroll
            for (int mt = 0; mt < 2; mt++) {
                int rbase = warp_m * 32 + mt * 16;
                uint32_t ad_h = (uint32_t)__cvta_generic_to_shared(
                    &Ah[rbase + arow_off][acol_off]);
                LDSM4(ah[mt][0], ah[mt][1], ah[mt][2], ah[mt][3], ad_h);
                uint32_t ad_l = (uint32_t)__cvta_generic_to_shared(
                    &Al[rbase + arow_off][acol_off]);
                LDSM4(al[mt][0], al[mt][1], al[mt][2], al[mt][3], ad_l);
            }

            uint32_t bh[8][2], bl[8][2];
#pragma unroll
            for (int np = 0; np < 4; np++) {
                int nbase = warp_n * 64 + np * 16;
                uint32_t r0, r1, r2, r3;
                uint32_t bd_h = (uint32_t)__cvta_generic_to_shared(
                    &Bh[nbase + arow_off][acol_off]);
                LDSM4(r0, r1, r2, r3, bd_h);
                bh[2 * np][0] = r0; bh[2 * np][1] = r2;
                bh[2 * np + 1][0] = r1; bh[2 * np + 1][1] = r3;
                uint32_t bd_l = (uint32_t)__cvta_generic_to_shared(
                    &Bl[nbase + arow_off][acol_off]);
                LDSM4(r0, r1, r2, r3, bd_l);
                bl[2 * np][0] = r0; bl[2 * np][1] = r2;
                bl[2 * np + 1][0] = r1; bl[2 * np + 1][1] = r3;
            }

#pragma unroll
            for (int mt = 0; mt < 2; mt++)
#pragma unroll
                for (int nt = 0; nt < 8; nt++) {
                    mma16816(acc[mt][nt], ah[mt], bh[nt]);
                    mma16816(acc[mt][nt], ah[mt], bl[nt]);
                    mma16816(acc[mt][nt], al[mt], bh[nt]);
                }
        }
        __syncthreads();
    }

    // ---- epilogue: bias + gelu, direct store ----
    const int g = lane >> 2;
    const int q2 = (lane & 3) * 2;
#pragma unroll
    for (int nt = 0; nt < 8; nt++) {
        int col = n0 + warp_n * 64 + nt * 8 + q2;
        float bias0 = bs[col] + bn[col];
        float bias1 = bs[col + 1] + bn[col + 1];
#pragma unroll
        for (int mt = 0; mt < 2; mt++) {
            int row = m0 + warp_m * 32 + mt * 16 + g;
            float2 o0, o1;
            o0.x = gelu_exact(acc[mt][nt][0] + bias0);
            o0.y = gelu_exact(acc[mt][nt][1] + bias1);
            o1.x = gelu_exact(acc[mt][nt][2] + bias0);
            o1.y = gelu_exact(acc[mt][nt][3] + bias1);
            *(float2*)(out + (size_t)row * CC + col) = o0;
            *(float2*)(out + (size_t)(row + 8) * CC + col) = o1;
        }
    }
}

// ================= launch =================
extern "C" void kernel_launch(void* const* d_in, const int* in_sizes, int n_in,
                              void* d_out, int out_size) {
    const float* x = 0; const void* ei = 0;
    const float* Ws = 0; const float* bsv = 0;
    const float* Wn = 0; const float* bnv = 0;
    for (int i = 0; i < n_in; i++) {
        int s = in_sizes[i];
        if (s == BB * NN * CC)      x = (const float*)d_in[i];
        else if (s == 2 * EE)       ei = d_in[i];
        else if (s == CC * CC) { if (!Ws) Ws = (const float*)d_in[i]; else Wn = (const float*)d_in[i]; }
        else if (s == CC)      { if (!bsv) bsv = (const float*)d_in[i]; else bnv = (const float*)d_in[i]; }
    }
    float* out = (float*)d_out;

    k_detect<<<1, 32>>>((const unsigned long long*)ei);
    k_zero<<<NN / 256, 256>>>();
    k_count<<<EE / 256, 256>>>(ei);
    k_scan<<<1, 1024>>>();
    k_scatter<<<EE / 256, 256>>>(ei);
    k_wprep<<<(KK * CC) / 256, 256>>>(Ws, Wn);

    k_agg<<<NN, 256>>>(x);

    dim3 ggrid(CC / GBN, MM / GBM);   // (2, 256)
    k_mma<<<ggrid, 256>>>(x, bsv, bnv, out);
}

// round 7
// speedup vs baseline: 1.5988x; 1.0884x over previous
#include <cuda_runtime.h>
#include <cuda_bf16.h>
#include <cuda_fp16.h>
#include <math.h>
#include <stdint.h>

#define NN 8192
#define BB 4
#define CC 256
#define EE 262144
#define MM (BB*NN)
#define KK 512          // GEMM K = 2*CC  ([x | y])

// ---- static scratch ----
__device__ int      g_is32;
__device__ int      g_cnt[NN];
__device__ int      g_rowptr[NN + 1];
__device__ int      g_cursor[NN];
__device__ float    g_invdeg[NN];
__device__ int      g_col[EE];
__device__ uint32_t g_xh[(size_t)MM * (CC/2)];     // x in fp16 (half2-packed)
__device__ float    g_y[(size_t)MM * CC];          // y = A_hat @ x
__device__ uint32_t g_whl[(size_t)CC * KK];        // W^T split: [n][k] packed (hi | lo<<16)

// ================= zero + edge dtype detection =================
__global__ void k_zero(const unsigned long long* __restrict__ ei) {
    int i = blockIdx.x * blockDim.x + threadIdx.x;
    if (i < NN) g_cnt[i] = 0;
    if (blockIdx.x == 0 && threadIdx.x == 0) {
        unsigned long long o = 0;
        for (int k = 0; k < 64; k++) o |= (ei[k] >> 32);
        g_is32 = (o != 0ull) ? 1 : 0;
    }
}

__device__ __forceinline__ int edge_at(const void* ei, int idx, int is32) {
    return is32 ? ((const int*)ei)[idx] : (int)((const long long*)ei)[idx];
}

__global__ void k_count(const void* __restrict__ ei) {
    int e = blockIdx.x * blockDim.x + threadIdx.x;
    if (e < EE) {
        int src = edge_at(ei, e, g_is32);
        if (src >= 0 && src < NN) atomicAdd(&g_cnt[src], 1);
    }
}

__global__ __launch_bounds__(1024)
void k_scan() {      // 1024 threads, 8 elems each
    __shared__ int wsum[32];
    int tid = threadIdx.x;
    int lane = tid & 31, warp = tid >> 5;
    int base = tid * 8;
    int local[8];
    int s = 0;
#pragma unroll
    for (int k = 0; k < 8; k++) { local[k] = s; s += g_cnt[base + k]; }
    int inc = s;
#pragma unroll
    for (int off = 1; off < 32; off <<= 1) {
        int v = __shfl_up_sync(0xffffffffu, inc, off);
        if (lane >= off) inc += v;
    }
    if (lane == 31) wsum[warp] = inc;
    __syncthreads();
    if (tid < 32) {
        int v = wsum[tid];
        int inc2 = v;
#pragma unroll
        for (int off = 1; off < 32; off <<= 1) {
            int u = __shfl_up_sync(0xffffffffu, inc2, off);
            if (tid >= off) inc2 += u;
        }
        wsum[tid] = inc2 - v;   // exclusive
    }
    __syncthreads();
    int off0 = wsum[warp] + (inc - s);
#pragma unroll
    for (int k = 0; k < 8; k++) {
        int rp = off0 + local[k];
        g_rowptr[base + k] = rp;
        g_cursor[base + k] = rp;
        g_invdeg[base + k] = 1.0f / (float)(g_cnt[base + k] + 1);
    }
    if (tid == 1023) g_rowptr[NN] = off0 + s;
}

__global__ void k_scatter(const void* __restrict__ ei) {
    int e = blockIdx.x * blockDim.x + threadIdx.x;
    if (e < EE) {
        int is32 = g_is32;
        int src = edge_at(ei, e, is32);
        int dst = edge_at(ei, EE + e, is32);
        if (src >= 0 && src < NN && dst >= 0 && dst < NN) {
            int pos = atomicAdd(&g_cursor[src], 1);
            if (pos >= 0 && pos < EE) g_col[pos] = dst;
        }
    }
}

// ================= x -> fp16 =================
__global__ __launch_bounds__(256)
void k_tofp16(const float* __restrict__ x) {
    int i = blockIdx.x * blockDim.x + threadIdx.x;   // over MM*CC/4 float4s
    float4 v = *(const float4*)(x + (size_t)i * 4);
    __half2 h0 = __floats2half2_rn(v.x, v.y);
    __half2 h1 = __floats2half2_rn(v.z, v.w);
    uint2 o;
    o.x = *(uint32_t*)&h0;
    o.y = *(uint32_t*)&h1;
    *(uint2*)(g_xh + (size_t)i * 2) = o;
}

// ================= W prep: concat, transpose, bf16 split =================
__global__ void k_wprep(const float* __restrict__ Ws, const float* __restrict__ Wn) {
    int i = blockIdx.x * blockDim.x + threadIdx.x;   // over 512*256
    if (i >= KK * CC) return;
    int k = i / CC;
    int n = i % CC;
    float w = (k < CC) ? Ws[(size_t)k * CC + n] : Wn[(size_t)(k - CC) * CC + n];
    __nv_bfloat16 h = __float2bfloat16(w);
    __nv_bfloat16 l = __float2bfloat16(w - __bfloat162float(h));
    uint32_t ph = (uint32_t)__bfloat16_as_ushort(h);
    uint32_t pl = (uint32_t)__bfloat16_as_ushort(l);
    g_whl[(size_t)n * KK + k] = ph | (pl << 16);
}

// ================= neighbor aggregation: y = A_hat @ x  (fp16 reads) =================
__global__ __launch_bounds__(128)
void k_agg() {
    int i = blockIdx.x;           // node
    int c2 = threadIdx.x;         // channel pair 0..127
    int start = g_rowptr[i];
    int end = g_rowptr[i + 1];
    float inv = g_invdeg[i];

    const uint32_t* x0 = g_xh + (size_t)(0 * NN) * (CC/2) + c2;
    const uint32_t* x1 = g_xh + (size_t)(1 * NN) * (CC/2) + c2;
    const uint32_t* x2 = g_xh + (size_t)(2 * NN) * (CC/2) + c2;
    const uint32_t* x3 = g_xh + (size_t)(3 * NN) * (CC/2) + c2;

    float2 a0, a1, a2, a3;
    {   // self loop
        size_t o = (size_t)i * (CC/2);
        a0 = __half22float2(*(const __half2*)&x0[o]);
        a1 = __half22float2(*(const __half2*)&x1[o]);
        a2 = __half22float2(*(const __half2*)&x2[o]);
        a3 = __half22float2(*(const __half2*)&x3[o]);
    }

#define ACC_EDGE(OFF)                                                  \
    {                                                                  \
        float2 t;                                                      \
        t = __half22float2(*(const __half2*)&x0[OFF]); a0.x += t.x; a0.y += t.y; \
        t = __half22float2(*(const __half2*)&x1[OFF]); a1.x += t.x; a1.y += t.y; \
        t = __half22float2(*(const __half2*)&x2[OFF]); a2.x += t.x; a2.y += t.y; \
        t = __half22float2(*(const __half2*)&x3[OFF]); a3.x += t.x; a3.y += t.y; \
    }

    int p = start;
    for (; p + 1 < end; p += 2) {
        size_t o0 = (size_t)g_col[p] * (CC/2);
        size_t o1 = (size_t)g_col[p + 1] * (CC/2);
        ACC_EDGE(o0);
        ACC_EDGE(o1);
    }
    if (p < end) {
        size_t o = (size_t)g_col[p] * (CC/2);
        ACC_EDGE(o);
    }
#undef ACC_EDGE

    int c = c2 * 2;
    float2 w0 = make_float2(a0.x * inv, a0.y * inv);
    float2 w1 = make_float2(a1.x * inv, a1.y * inv);
    float2 w2 = make_float2(a2.x * inv, a2.y * inv);
    float2 w3 = make_float2(a3.x * inv, a3.y * inv);
    *(float2*)(g_y + ((size_t)(0 * NN + i)) * CC + c) = w0;
    *(float2*)(g_y + ((size_t)(1 * NN + i)) * CC + c) = w1;
    *(float2*)(g_y + ((size_t)(2 * NN + i)) * CC + c) = w2;
    *(float2*)(g_y + ((size_t)(3 * NN + i)) * CC + c) = w3;
}

// ================= tensor-core GEMM + bias + GELU =================
#define GBM 128
#define GBN 128
#define GBK 32
#define KTILES (KK / GBK)   // 16
#define APAD 8              // row stride 40 bf16 = 80B: 16B-aligned rows for ldmatrix

__device__ __forceinline__ void mma16816(float* c, const uint32_t* a, const uint32_t* b) {
    asm volatile(
        "mma.sync.aligned.m16n8k16.row.col.f32.bf16.bf16.f32 "
        "{%0,%1,%2,%3}, {%4,%5,%6,%7}, {%8,%9}, {%0,%1,%2,%3};"
        : "+f"(c[0]), "+f"(c[1]), "+f"(c[2]), "+f"(c[3])
        : "r"(a[0]), "r"(a[1]), "r"(a[2]), "r"(a[3]), "r"(b[0]), "r"(b[1]));
}

#define LDSM4(r0, r1, r2, r3, addr) \
    asm volatile("ldmatrix.sync.aligned.m8n8.x4.shared.b16 {%0,%1,%2,%3}, [%4];" \
                 : "=r"(r0), "=r"(r1), "=r"(r2), "=r"(r3) : "r"(addr))

__device__ __forceinline__ float gelu_exact(float z) {
    return 0.5f * z * (1.0f + erff(z * 0.70710678118654752440f));
}

__global__ __launch_bounds__(256, 1)
void k_mma(const float* __restrict__ x,
           const float* __restrict__ bs, const float* __restrict__ bn,
           float* __restrict__ out) {
    __shared__ __align__(16) __nv_bfloat16 Ah[GBM][GBK + APAD];
    __shared__ __align__(16) __nv_bfloat16 Al[GBM][GBK + APAD];
    __shared__ __align__(16) __nv_bfloat16 Bh[GBN][GBK + APAD];
    __shared__ __align__(16) __nv_bfloat16 Bl[GBN][GBK + APAD];

    const int tid = threadIdx.x;
    const int lane = tid & 31;
    const int warp = tid >> 5;
    const int warp_m = warp & 3;        // 4 warps along M (32 rows each)
    const int warp_n = warp >> 2;       // 2 warps along N (64 cols each)
    const int n0 = blockIdx.x * GBN;    // 0 or 128
    const int m0 = blockIdx.y * GBM;

    const int a_r = tid >> 3;           // 0..31
    const int a_k = (tid & 7) * 4;      // 0,4,...,28
    const int w_n = tid >> 1;           // 0..127
    const int w_k = (tid & 1) * 16;     // 0 or 16

    float acc[2][8][4];
#pragma unroll
    for (int i = 0; i < 2; i++)
#pragma unroll
        for (int j = 0; j < 8; j++)
#pragma unroll
            for (int q = 0; q < 4; q++) acc[i][j][q] = 0.0f;

    float4 pa[4];
    uint4  pw[4];

    // ---- prefetch tile 0 ----
    {
        const float* Asrc = x;
#pragma unroll
        for (int p = 0; p < 4; p++)
            pa[p] = *(const float4*)(Asrc + (size_t)(m0 + p * 32 + a_r) * CC + a_k);
        const uint32_t* wp = g_whl + (size_t)(n0 + w_n) * KK + w_k;
#pragma unroll
        for (int q = 0; q < 4; q++) pw[q] = *(const uint4*)(wp + q * 4);
    }

    for (int kt = 0; kt < KTILES; kt++) {
        // ---- store smem (fp32->bf16 hi/lo split for A) ----
#pragma unroll
        for (int p = 0; p < 4; p++) {
            int r = p * 32 + a_r;
            float v[4] = {pa[p].x, pa[p].y, pa[p].z, pa[p].w};
#pragma unroll
            for (int e = 0; e < 4; e++) {
                __nv_bfloat16 h = __float2bfloat16(v[e]);
                __nv_bfloat16 l = __float2bfloat16(v[e] - __bfloat162float(h));
                Ah[r][a_k + e] = h;
                Al[r][a_k + e] = l;
            }
        }
#pragma unroll
        for (int q = 0; q < 4; q++) {
            uint32_t ww[4] = {pw[q].x, pw[q].y, pw[q].z, pw[q].w};
#pragma unroll
            for (int e = 0; e < 4; e++) {
                int kk = w_k + q * 4 + e;
                Bh[w_n][kk] = __ushort_as_bfloat16((unsigned short)(ww[e] & 0xffffu));
                Bl[w_n][kk] = __ushort_as_bfloat16((unsigned short)(ww[e] >> 16));
            }
        }
        __syncthreads();

        // ---- prefetch next tile ----
        if (kt + 1 < KTILES) {
            int k0 = (kt + 1) * GBK;
            const float* Asrc = (k0 < CC) ? (x + k0) : (g_y + (k0 - CC));
#pragma unroll
            for (int p = 0; p < 4; p++)
                pa[p] = *(const float4*)(Asrc + (size_t)(m0 + p * 32 + a_r) * CC + a_k);
            const uint32_t* wp = g_whl + (size_t)(n0 + w_n) * KK + k0 + w_k;
#pragma unroll
            for (int q = 0; q < 4; q++) pw[q] = *(const uint4*)(wp + q * 4);
        }

        // ---- compute: 2 k16 steps ----
#pragma unroll
        for (int s = 0; s < 2; s++) {
            const int kb = s * 16;
            const int sub = lane >> 3;
            const int l8 = lane & 7;
            const int arow_off = (sub & 1) * 8 + l8;
            const int acol_off = kb + (sub >> 1) * 8;

            uint32_t ah[2][4], al[2][4];
#pragma unroll
            for (int mt = 0; mt < 2; mt++) {
                int rbase = warp_m * 32 + mt * 16;
                uint32_t ad_h = (uint32_t)__cvta_generic_to_shared(
                    &Ah[rbase + arow_off][acol_off]);
                LDSM4(ah[mt][0], ah[mt][1], ah[mt][2], ah[mt][3], ad_h);
                uint32_t ad_l = (uint32_t)__cvta_generic_to_shared(
                    &Al[rbase + arow_off][acol_off]);
                LDSM4(al[mt][0], al[mt][1], al[mt][2], al[mt][3], ad_l);
            }

            uint32_t bh[8][2], bl[8][2];
#pragma unroll
            for (int np = 0; np < 4; np++) {
                int nbase = warp_n * 64 + np * 16;
                uint32_t r0, r1, r2, r3;
                uint32_t bd_h = (uint32_t)__cvta_generic_to_shared(
                    &Bh[nbase + arow_off][acol_off]);
                LDSM4(r0, r1, r2, r3, bd_h);
                bh[2 * np][0] = r0; bh[2 * np][1] = r2;
                bh[2 * np + 1][0] = r1; bh[2 * np + 1][1] = r3;
                uint32_t bd_l = (uint32_t)__cvta_generic_to_shared(
                    &Bl[nbase + arow_off][acol_off]);
                LDSM4(r0, r1, r2, r3, bd_l);
                bl[2 * np][0] = r0; bl[2 * np][1] = r2;
                bl[2 * np + 1][0] = r1; bl[2 * np + 1][1] = r3;
            }

#pragma unroll
            for (int mt = 0; mt < 2; mt++)
#pragma unroll
                for (int nt = 0; nt < 8; nt++) {
                    mma16816(acc[mt][nt], ah[mt], bh[nt]);
                    mma16816(acc[mt][nt], ah[mt], bl[nt]);
                    mma16816(acc[mt][nt], al[mt], bh[nt]);
                }
        }
        __syncthreads();
    }

    // ---- epilogue: bias + gelu, direct store ----
    const int g = lane >> 2;
    const int q2 = (lane & 3) * 2;
#pragma unroll
    for (int nt = 0; nt < 8; nt++) {
        int col = n0 + warp_n * 64 + nt * 8 + q2;
        float bias0 = bs[col] + bn[col];
        float bias1 = bs[col + 1] + bn[col + 1];
#pragma unroll
        for (int mt = 0; mt < 2; mt++) {
            int row = m0 + warp_m * 32 + mt * 16 + g;
            float2 o0, o1;
            o0.x = gelu_exact(acc[mt][nt][0] + bias0);
            o0.y = gelu_exact(acc[mt][nt][1] + bias1);
            o1.x = gelu_exact(acc[mt][nt][2] + bias0);
            o1.y = gelu_exact(acc[mt][nt][3] + bias1);
            *(float2*)(out + (size_t)row * CC + col) = o0;
            *(float2*)(out + (size_t)(row + 8) * CC + col) = o1;
        }
    }
}

// ================= launch =================
extern "C" void kernel_launch(void* const* d_in, const int* in_sizes, int n_in,
                              void* d_out, int out_size) {
    const float* x = 0; const void* ei = 0;
    const float* Ws = 0; const float* bsv = 0;
    const float* Wn = 0; const float* bnv = 0;
    for (int i = 0; i < n_in; i++) {
        int s = in_sizes[i];
        if (s == BB * NN * CC)      x = (const float*)d_in[i];
        else if (s == 2 * EE)       ei = d_in[i];
        else if (s == CC * CC) { if (!Ws) Ws = (const float*)d_in[i]; else Wn = (const float*)d_in[i]; }
        else if (s == CC)      { if (!bsv) bsv = (const float*)d_in[i]; else bnv = (const float*)d_in[i]; }
    }
    float* out = (float*)d_out;

    k_zero<<<NN / 256, 256>>>((const unsigned long long*)ei);
    k_count<<<EE / 256, 256>>>(ei);
    k_scan<<<1, 1024>>>();
    k_scatter<<<EE / 256, 256>>>(ei);
    k_tofp16<<<(MM * CC / 4) / 256, 256>>>(x);
    k_wprep<<<(KK * CC) / 256, 256>>>(Ws, Wn);

    k_agg<<<NN, 128>>>();

    dim3 ggrid(CC / GBN, MM / GBM);   // (2, 256)
    k_mma<<<ggrid, 256>>>(x, bsv, bnv, out);
}

// round 8
// speedup vs baseline: 1.6553x; 1.0354x over previous
#include <cuda_runtime.h>
#include <cuda_bf16.h>
#include <cuda_fp16.h>
#include <math.h>
#include <stdint.h>

#define NN 8192
#define BB 4
#define CC 256
#define EE 262144
#define MM (BB*NN)
#define KK 512          // GEMM K = 2*CC  ([x | y])

// ---- static scratch ----
__device__ int      g_is32;
__device__ int      g_cnt[NN];
__device__ int      g_rowptr[NN + 1];
__device__ int      g_cursor[NN];
__device__ float    g_invdeg[NN];
__device__ int      g_col[EE];
__device__ uint32_t g_xh[(size_t)MM * (CC/2)];     // x in fp16 (half2-packed), for agg
__device__ uint32_t g_ahl[(size_t)MM * KK];        // GEMM A, bf16 split packed: [m][k] (hi | lo<<16)
__device__ uint32_t g_whl[(size_t)CC * KK];        // W^T split: [n][k] packed (hi | lo<<16)
__device__ float    g_bias[CC];                    // b_self + b_neigh

__device__ __forceinline__ uint32_t pack_split(float v) {
    __nv_bfloat16 h = __float2bfloat16(v);
    __nv_bfloat16 l = __float2bfloat16(v - __bfloat162float(h));
    return (uint32_t)__bfloat16_as_ushort(h) | ((uint32_t)__bfloat16_as_ushort(l) << 16);
}

// ================= fused prep: zero + detect + x->fp16 + x->split + W prep + bias =================
__global__ __launch_bounds__(256)
void k_prep(const float* __restrict__ x, const unsigned long long* __restrict__ ei,
            const float* __restrict__ Ws, const float* __restrict__ Wn,
            const float* __restrict__ bs, const float* __restrict__ bn) {
    int i = blockIdx.x * 256 + threadIdx.x;   // 0 .. MM*CC/4-1  (2,097,152)

    // x conversion: 4 elems per thread
    {
        float4 v = *(const float4*)(x + (size_t)i * 4);
        __half2 h0 = __floats2half2_rn(v.x, v.y);
        __half2 h1 = __floats2half2_rn(v.z, v.w);
        uint2 o;
        o.x = *(uint32_t*)&h0;
        o.y = *(uint32_t*)&h1;
        *(uint2*)(g_xh + (size_t)i * 2) = o;

        int e4 = i * 4;
        int m = e4 >> 8;          // /CC
        int k = e4 & 255;         // %CC
        uint4 pk;
        pk.x = pack_split(v.x);
        pk.y = pack_split(v.y);
        pk.z = pack_split(v.z);
        pk.w = pack_split(v.w);
        *(uint4*)(g_ahl + (size_t)m * KK + k) = pk;
    }

    if (i < NN) g_cnt[i] = 0;

    if (i < KK * CC) {            // W prep
        int k = i / CC;
        int n = i % CC;
        float w = (k < CC) ? Ws[(size_t)k * CC + n] : Wn[(size_t)(k - CC) * CC + n];
        g_whl[(size_t)n * KK + k] = pack_split(w);
    }

    if (i < CC) g_bias[i] = bs[i] + bn[i];

    if (i == 0) {
        unsigned long long o = 0;
        for (int k = 0; k < 64; k++) o |= (ei[k] >> 32);
        g_is32 = (o != 0ull) ? 1 : 0;
    }
}

// ================= CSR build =================
__device__ __forceinline__ int edge_at(const void* ei, int idx, int is32) {
    return is32 ? ((const int*)ei)[idx] : (int)((const long long*)ei)[idx];
}

__global__ void k_count(const void* __restrict__ ei) {
    int e = blockIdx.x * blockDim.x + threadIdx.x;
    if (e < EE) {
        int src = edge_at(ei, e, g_is32);
        if (src >= 0 && src < NN) atomicAdd(&g_cnt[src], 1);
    }
}

__global__ __launch_bounds__(1024)
void k_scan() {      // 1024 threads, 8 elems each
    __shared__ int wsum[32];
    int tid = threadIdx.x;
    int lane = tid & 31, warp = tid >> 5;
    int base = tid * 8;
    int local[8];
    int s = 0;
#pragma unroll
    for (int k = 0; k < 8; k++) { local[k] = s; s += g_cnt[base + k]; }
    int inc = s;
#pragma unroll
    for (int off = 1; off < 32; off <<= 1) {
        int v = __shfl_up_sync(0xffffffffu, inc, off);
        if (lane >= off) inc += v;
    }
    if (lane == 31) wsum[warp] = inc;
    __syncthreads();
    if (tid < 32) {
        int v = wsum[tid];
        int inc2 = v;
#pragma unroll
        for (int off = 1; off < 32; off <<= 1) {
            int u = __shfl_up_sync(0xffffffffu, inc2, off);
            if (tid >= off) inc2 += u;
        }
        wsum[tid] = inc2 - v;   // exclusive
    }
    __syncthreads();
    int off0 = wsum[warp] + (inc - s);
#pragma unroll
    for (int k = 0; k < 8; k++) {
        int rp = off0 + local[k];
        g_rowptr[base + k] = rp;
        g_cursor[base + k] = rp;
        g_invdeg[base + k] = 1.0f / (float)(g_cnt[base + k] + 1);
    }
    if (tid == 1023) g_rowptr[NN] = off0 + s;
}

__global__ void k_scatter(const void* __restrict__ ei) {
    int e = blockIdx.x * blockDim.x + threadIdx.x;
    if (e < EE) {
        int is32 = g_is32;
        int src = edge_at(ei, e, is32);
        int dst = edge_at(ei, EE + e, is32);
        if (src >= 0 && src < NN && dst >= 0 && dst < NN) {
            int pos = atomicAdd(&g_cursor[src], 1);
            if (pos >= 0 && pos < EE) g_col[pos] = dst;
        }
    }
}

// ================= neighbor aggregation: y = A_hat @ x  (fp16 reads, packed-split writes) =================
__global__ __launch_bounds__(128)
void k_agg() {
    int i = blockIdx.x;           // node
    int c2 = threadIdx.x;         // channel pair 0..127
    int start = g_rowptr[i];
    int end = g_rowptr[i + 1];
    float inv = g_invdeg[i];

    const uint32_t* x0 = g_xh + (size_t)(0 * NN) * (CC/2) + c2;
    const uint32_t* x1 = g_xh + (size_t)(1 * NN) * (CC/2) + c2;
    const uint32_t* x2 = g_xh + (size_t)(2 * NN) * (CC/2) + c2;
    const uint32_t* x3 = g_xh + (size_t)(3 * NN) * (CC/2) + c2;

    float2 a0, a1, a2, a3;
    {   // self loop
        size_t o = (size_t)i * (CC/2);
        a0 = __half22float2(*(const __half2*)&x0[o]);
        a1 = __half22float2(*(const __half2*)&x1[o]);
        a2 = __half22float2(*(const __half2*)&x2[o]);
        a3 = __half22float2(*(const __half2*)&x3[o]);
    }

#define ACC_EDGE(OFF)                                                  \
    {                                                                  \
        float2 t;                                                      \
        t = __half22float2(*(const __half2*)&x0[OFF]); a0.x += t.x; a0.y += t.y; \
        t = __half22float2(*(const __half2*)&x1[OFF]); a1.x += t.x; a1.y += t.y; \
        t = __half22float2(*(const __half2*)&x2[OFF]); a2.x += t.x; a2.y += t.y; \
        t = __half22float2(*(const __half2*)&x3[OFF]); a3.x += t.x; a3.y += t.y; \
    }

    int p = start;
    for (; p + 1 < end; p += 2) {
        size_t o0 = (size_t)g_col[p] * (CC/2);
        size_t o1 = (size_t)g_col[p + 1] * (CC/2);
        ACC_EDGE(o0);
        ACC_EDGE(o1);
    }
    if (p < end) {
        size_t o = (size_t)g_col[p] * (CC/2);
        ACC_EDGE(o);
    }
#undef ACC_EDGE

    int c = CC + c2 * 2;          // y occupies cols 256..511 of g_ahl
    uint2 w0, w1, w2, w3;
    w0.x = pack_split(a0.x * inv); w0.y = pack_split(a0.y * inv);
    w1.x = pack_split(a1.x * inv); w1.y = pack_split(a1.y * inv);
    w2.x = pack_split(a2.x * inv); w2.y = pack_split(a2.y * inv);
    w3.x = pack_split(a3.x * inv); w3.y = pack_split(a3.y * inv);
    *(uint2*)(g_ahl + ((size_t)(0 * NN + i)) * KK + c) = w0;
    *(uint2*)(g_ahl + ((size_t)(1 * NN + i)) * KK + c) = w1;
    *(uint2*)(g_ahl + ((size_t)(2 * NN + i)) * KK + c) = w2;
    *(uint2*)(g_ahl + ((size_t)(3 * NN + i)) * KK + c) = w3;
}

// ================= tensor-core GEMM + bias + GELU =================
#define GBM 128
#define GBN 128
#define GBK 32
#define KTILES (KK / GBK)   // 16
#define APAD 8              // row stride 40 bf16 = 80B: 16B-aligned, ldmatrix conflict-free

__device__ __forceinline__ void mma16816(float* c, const uint32_t* a, const uint32_t* b) {
    asm volatile(
        "mma.sync.aligned.m16n8k16.row.col.f32.bf16.bf16.f32 "
        "{%0,%1,%2,%3}, {%4,%5,%6,%7}, {%8,%9}, {%0,%1,%2,%3};"
        : "+f"(c[0]), "+f"(c[1]), "+f"(c[2]), "+f"(c[3])
        : "r"(a[0]), "r"(a[1]), "r"(a[2]), "r"(a[3]), "r"(b[0]), "r"(b[1]));
}

#define LDSM4(r0, r1, r2, r3, addr) \
    asm volatile("ldmatrix.sync.aligned.m8n8.x4.shared.b16 {%0,%1,%2,%3}, [%4];" \
                 : "=r"(r0), "=r"(r1), "=r"(r2), "=r"(r3) : "r"(addr))

__device__ __forceinline__ float gelu_exact(float z) {
    return 0.5f * z * (1.0f + erff(z * 0.70710678118654752440f));
}

__global__ __launch_bounds__(256, 1)
void k_mma(float* __restrict__ out) {
    __shared__ __align__(16) __nv_bfloat16 Ah[GBM][GBK + APAD];
    __shared__ __align__(16) __nv_bfloat16 Al[GBM][GBK + APAD];
    __shared__ __align__(16) __nv_bfloat16 Bh[GBN][GBK + APAD];
    __shared__ __align__(16) __nv_bfloat16 Bl[GBN][GBK + APAD];

    const int tid = threadIdx.x;
    const int lane = tid & 31;
    const int warp = tid >> 5;
    const int warp_m = warp & 3;        // 4 warps along M (32 rows each)
    const int warp_n = warp >> 2;       // 2 warps along N (64 cols each)
    const int n0 = blockIdx.x * GBN;    // 0 or 128
    const int m0 = blockIdx.y * GBM;

    const int a_r = tid >> 3;           // 0..31
    const int a_k = (tid & 7) * 4;      // 0,4,...,28
    const int w_n = tid >> 1;           // 0..127
    const int w_k = (tid & 1) * 16;     // 0 or 16

    float acc[2][8][4];
#pragma unroll
    for (int i = 0; i < 2; i++)
#pragma unroll
        for (int j = 0; j < 8; j++)
#pragma unroll
            for (int q = 0; q < 4; q++) acc[i][j][q] = 0.0f;

    uint4 pa[4];
    uint4 pw[4];

    // ---- prefetch tile 0 ----
#pragma unroll
    for (int p = 0; p < 4; p++)
        pa[p] = *(const uint4*)(g_ahl + (size_t)(m0 + p * 32 + a_r) * KK + a_k);
    {
        const uint32_t* wp = g_whl + (size_t)(n0 + w_n) * KK + w_k;
#pragma unroll
        for (int q = 0; q < 4; q++) pw[q] = *(const uint4*)(wp + q * 4);
    }

    for (int kt = 0; kt < KTILES; kt++) {
        // ---- store smem (unpack hi/lo) ----
#pragma unroll
        for (int p = 0; p < 4; p++) {
            int r = p * 32 + a_r;
            uint32_t vv[4] = {pa[p].x, pa[p].y, pa[p].z, pa[p].w};
#pragma unroll
            for (int e = 0; e < 4; e++) {
                Ah[r][a_k + e] = __ushort_as_bfloat16((unsigned short)(vv[e] & 0xffffu));
                Al[r][a_k + e] = __ushort_as_bfloat16((unsigned short)(vv[e] >> 16));
            }
        }
#pragma unroll
        for (int q = 0; q < 4; q++) {
            uint32_t ww[4] = {pw[q].x, pw[q].y, pw[q].z, pw[q].w};
#pragma unroll
            for (int e = 0; e < 4; e++) {
                int kk = w_k + q * 4 + e;
                Bh[w_n][kk] = __ushort_as_bfloat16((unsigned short)(ww[e] & 0xffffu));
                Bl[w_n][kk] = __ushort_as_bfloat16((unsigned short)(ww[e] >> 16));
            }
        }
        __syncthreads();

        // ---- prefetch next tile ----
        if (kt + 1 < KTILES) {
            int k0 = (kt + 1) * GBK;
#pragma unroll
            for (int p = 0; p < 4; p++)
                pa[p] = *(const uint4*)(g_ahl + (size_t)(m0 + p * 32 + a_r) * KK + k0 + a_k);
            const uint32_t* wp = g_whl + (size_t)(n0 + w_n) * KK + k0 + w_k;
#pragma unroll
            for (int q = 0; q < 4; q++) pw[q] = *(const uint4*)(wp + q * 4);
        }

        // ---- compute: 2 k16 steps ----
#pragma unroll
        for (int s = 0; s < 2; s++) {
            const int kb = s * 16;
            const int sub = lane >> 3;
            const int l8 = lane & 7;
            const int arow_off = (sub & 1) * 8 + l8;
            const int acol_off = kb + (sub >> 1) * 8;

            uint32_t ah[2][4], al[2][4];
#pragma unroll
            for (int mt = 0; mt < 2; mt++) {
                int rbase = warp_m * 32 + mt * 16;
                uint32_t ad_h = (uint32_t)__cvta_generic_to_shared(
                    &Ah[rbase + arow_off][acol_off]);
                LDSM4(ah[mt][0], ah[mt][1], ah[mt][2], ah[mt][3], ad_h);
                uint32_t ad_l = (uint32_t)__cvta_generic_to_shared(
                    &Al[rbase + arow_off][acol_off]);
                LDSM4(al[mt][0], al[mt][1], al[mt][2], al[mt][3], ad_l);
            }

            uint32_t bh[8][2], bl[8][2];
#pragma unroll
            for (int np = 0; np < 4; np++) {
                int nbase = warp_n * 64 + np * 16;
                uint32_t r0, r1, r2, r3;
                uint32_t bd_h = (uint32_t)__cvta_generic_to_shared(
                    &Bh[nbase + arow_off][acol_off]);
                LDSM4(r0, r1, r2, r3, bd_h);
                bh[2 * np][0] = r0; bh[2 * np][1] = r2;
                bh[2 * np + 1][0] = r1; bh[2 * np + 1][1] = r3;
                uint32_t bd_l = (uint32_t)__cvta_generic_to_shared(
                    &Bl[nbase + arow_off][acol_off]);
                LDSM4(r0, r1, r2, r3, bd_l);
                bl[2 * np][0] = r0; bl[2 * np][1] = r2;
                bl[2 * np + 1][0] = r1; bl[2 * np + 1][1] = r3;
            }

#pragma unroll
            for (int mt = 0; mt < 2; mt++)
#pragma unroll
                for (int nt = 0; nt < 8; nt++) {
                    mma16816(acc[mt][nt], ah[mt], bh[nt]);
                    mma16816(acc[mt][nt], ah[mt], bl[nt]);
                    mma16816(acc[mt][nt], al[mt], bh[nt]);
                }
        }
        __syncthreads();
    }

    // ---- epilogue: bias + gelu, direct store ----
    const int g = lane >> 2;
    const int q2 = (lane & 3) * 2;
#pragma unroll
    for (int nt = 0; nt < 8; nt++) {
        int col = n0 + warp_n * 64 + nt * 8 + q2;
        float bias0 = g_bias[col];
        float bias1 = g_bias[col + 1];
#pragma unroll
        for (int mt = 0; mt < 2; mt++) {
            int row = m0 + warp_m * 32 + mt * 16 + g;
            float2 o0, o1;
            o0.x = gelu_exact(acc[mt][nt][0] + bias0);
            o0.y = gelu_exact(acc[mt][nt][1] + bias1);
            o1.x = gelu_exact(acc[mt][nt][2] + bias0);
            o1.y = gelu_exact(acc[mt][nt][3] + bias1);
            *(float2*)(out + (size_t)row * CC + col) = o0;
            *(float2*)(out + (size_t)(row + 8) * CC + col) = o1;
        }
    }
}

// ================= launch =================
extern "C" void kernel_launch(void* const* d_in, const int* in_sizes, int n_in,
                              void* d_out, int out_size) {
    const float* x = 0; const void* ei = 0;
    const float* Ws = 0; const float* bsv = 0;
    const float* Wn = 0; const float* bnv = 0;
    for (int i = 0; i < n_in; i++) {
        int s = in_sizes[i];
        if (s == BB * NN * CC)      x = (const float*)d_in[i];
        else if (s == 2 * EE)       ei = d_in[i];
        else if (s == CC * CC) { if (!Ws) Ws = (const float*)d_in[i]; else Wn = (const float*)d_in[i]; }
        else if (s == CC)      { if (!bsv) bsv = (const float*)d_in[i]; else bnv = (const float*)d_in[i]; }
    }
    float* out = (float*)d_out;

    k_prep<<<(MM * CC / 4) / 256, 256>>>(x, (const unsigned long long*)ei, Ws, Wn, bsv, bnv);
    k_count<<<EE / 256, 256>>>(ei);
    k_scan<<<1, 1024>>>();
    k_scatter<<<EE / 256, 256>>>(ei);

    k_agg<<<NN, 128>>>();

    dim3 ggrid(CC / GBN, MM / GBM);   // (2, 256)
    k_mma<<<ggrid, 256>>>(out);
}